// round 1
// baseline (speedup 1.0000x reference)
#include <cuda_runtime.h>
#include <math_constants.h>

// Problem constants
#define NPTS   100000
#define BATCH  4096
#define TOPK   10

// Tiling
#define NCHUNK 16                 // point chunks
#define PC     6256               // points per chunk (mult of 16), NCHUNK*PC = 100096 >= NPTS
#define NPAD   (NCHUNK * PC)      // padded point count
#define NGROUP 128                // ray groups of 32 rays (NGROUP*32 = BATCH)
#define GROUPS_PER_BLOCK 8        // warps per block in main kernel

// Scratch (device globals; no allocation allowed)
__device__ float4 g_pts[NPAD];                         // (x, y, z, |p|^2), padded with w=+INF
__device__ float  g_cand_t[BATCH * NCHUNK * TOPK];     // partial top-K keys (t = |p|^2 - 2 c.p)
__device__ int    g_cand_i[BATCH * NCHUNK * TOPK];     // partial top-K indices

// ---------------------------------------------------------------------------
// Prep: pack points as float4 with precomputed squared norm; pad with +INF.
// ---------------------------------------------------------------------------
__global__ void prep_kernel(const float* __restrict__ xyz) {
    int i = blockIdx.x * blockDim.x + threadIdx.x;
    if (i >= NPAD) return;
    if (i < NPTS) {
        float x = xyz[3 * i + 0];
        float y = xyz[3 * i + 1];
        float z = xyz[3 * i + 2];
        float w = fmaf(x, x, fmaf(y, y, z * z));
        g_pts[i] = make_float4(x, y, z, w);
    } else {
        g_pts[i] = make_float4(0.f, 0.f, 0.f, CUDART_INF_F);
    }
}

// ---------------------------------------------------------------------------
// Sorted top-10 insert (ascending). Caller guarantees t < d[9].
// Early-exit shift; arrays stay in registers (full unroll, static indices).
// Tie rule: strict < keeps earlier (lower-index) entries first, matching
// jax.lax.top_k stability given in-index-order scanning.
// ---------------------------------------------------------------------------
__device__ __forceinline__ void insert10(float t, int i, float (&d)[TOPK], int (&id)[TOPK]) {
#pragma unroll
    for (int j = TOPK - 1; j > 0; --j) {
        if (t < d[j - 1]) {
            d[j]  = d[j - 1];
            id[j] = id[j - 1];
        } else {
            d[j]  = t;
            id[j] = i;
            return;
        }
    }
    d[0]  = t;
    id[0] = i;
}

// ---------------------------------------------------------------------------
// Main scan: warp = 32 rays (lane-per-ray), each warp scans one point chunk.
// All lanes load the SAME point (uniform address -> one 16B line per warp).
// Ranking key t = |p|^2 - 2 c.p  (ordering identical to squared distance).
// ---------------------------------------------------------------------------
__global__ void __launch_bounds__(GROUPS_PER_BLOCK * 32)
scan_kernel(const float* __restrict__ rays_o, const float* __restrict__ rays_d) {
    const int warp  = threadIdx.x >> 5;
    const int lane  = threadIdx.x & 31;
    const int group = blockIdx.x * GROUPS_PER_BLOCK + warp;   // [0, NGROUP)
    const int chunk = blockIdx.y;                              // [0, NCHUNK)
    const int ray   = group * 32 + lane;                       // [0, BATCH)

    // Ray center c = o + 3 d ; fold the -2 into per-lane constants.
    const float cx = fmaf(3.0f, rays_d[3 * ray + 0], rays_o[3 * ray + 0]);
    const float cy = fmaf(3.0f, rays_d[3 * ray + 1], rays_o[3 * ray + 1]);
    const float cz = fmaf(3.0f, rays_d[3 * ray + 2], rays_o[3 * ray + 2]);
    const float mx = -2.0f * cx;
    const float my = -2.0f * cy;
    const float mz = -2.0f * cz;

    float d[TOPK];
    int   id[TOPK];
#pragma unroll
    for (int j = 0; j < TOPK; ++j) { d[j] = CUDART_INF_F; id[j] = 0; }

    const float4* __restrict__ pts = g_pts;
    const int start = chunk * PC;
    const int end   = start + PC;

    for (int i = start; i < end; i += 4) {
        // 4 independent uniform loads up front (MLP=4)
        float4 p0 = pts[i + 0];
        float4 p1 = pts[i + 1];
        float4 p2 = pts[i + 2];
        float4 p3 = pts[i + 3];

        float t0 = fmaf(p0.x, mx, fmaf(p0.y, my, fmaf(p0.z, mz, p0.w)));
        float t1 = fmaf(p1.x, mx, fmaf(p1.y, my, fmaf(p1.z, mz, p1.w)));
        float t2 = fmaf(p2.x, mx, fmaf(p2.y, my, fmaf(p2.z, mz, p2.w)));
        float t3 = fmaf(p3.x, mx, fmaf(p3.y, my, fmaf(p3.z, mz, p3.w)));

        if (t0 < d[TOPK - 1]) insert10(t0, i + 0, d, id);
        if (t1 < d[TOPK - 1]) insert10(t1, i + 1, d, id);
        if (t2 < d[TOPK - 1]) insert10(t2, i + 2, d, id);
        if (t3 < d[TOPK - 1]) insert10(t3, i + 3, d, id);
    }

    // Spill partial top-10 for this (ray, chunk)
    const int base = (ray * NCHUNK + chunk) * TOPK;
#pragma unroll
    for (int j = 0; j < TOPK; ++j) {
        g_cand_t[base + j] = d[j];
        g_cand_i[base + j] = id[j];
    }
}

// ---------------------------------------------------------------------------
// Merge partials + epilogue. Thread per ray.
// ---------------------------------------------------------------------------
__global__ void __launch_bounds__(256)
merge_kernel(const float* __restrict__ rays_o, const float* __restrict__ rays_d,
             const float* __restrict__ features_dc, const float* __restrict__ opacity,
             float* __restrict__ out) {
    const int ray = blockIdx.x * blockDim.x + threadIdx.x;
    if (ray >= BATCH) return;

    float d[TOPK];
    int   id[TOPK];
#pragma unroll
    for (int j = 0; j < TOPK; ++j) { d[j] = CUDART_INF_F; id[j] = 0; }

    // Merge NCHUNK partial sorted lists (processed chunk-ascending; within a
    // chunk entries are sorted ascending and index-ordered -> stable overall).
    const int base = ray * NCHUNK * TOPK;
    for (int c = 0; c < NCHUNK; ++c) {
#pragma unroll
        for (int j = 0; j < TOPK; ++j) {
            float t = g_cand_t[base + c * TOPK + j];
            if (t < d[TOPK - 1]) insert10(t, g_cand_i[base + c * TOPK + j], d, id);
            else break;  // list sorted ascending; the rest can't enter
        }
    }

    // Ray center and its squared norm (key t stored |p|^2 - 2 c.p; add |c|^2 back)
    const float cx = fmaf(3.0f, rays_d[3 * ray + 0], rays_o[3 * ray + 0]);
    const float cy = fmaf(3.0f, rays_d[3 * ray + 1], rays_o[3 * ray + 1]);
    const float cz = fmaf(3.0f, rays_d[3 * ray + 2], rays_o[3 * ray + 2]);
    const float c2 = fmaf(cx, cx, fmaf(cy, cy, cz * cz));

    float wsum = 0.0f;
    float r = 0.0f, g = 0.0f, b = 0.0f;
#pragma unroll
    for (int j = 0; j < TOPK; ++j) {
        const int   k    = id[j];
        const float sq   = fmaxf(d[j] + c2, 0.0f);
        const float dist = sqrtf(sq);
        const float op   = 1.0f / (1.0f + expf(-opacity[k]));
        const float w    = expf(-0.1f * dist) * op;
        wsum += w;
        const float fr = features_dc[3 * k + 0];
        const float fg = features_dc[3 * k + 1];
        const float fb = features_dc[3 * k + 2];
        r = fmaf(w, 1.0f / (1.0f + expf(-fr)), r);
        g = fmaf(w, 1.0f / (1.0f + expf(-fg)), g);
        b = fmaf(w, 1.0f / (1.0f + expf(-fb)), b);
    }
    const float inv = 1.0f / (wsum + 1e-8f);
    out[3 * ray + 0] = r * inv;
    out[3 * ray + 1] = g * inv;
    out[3 * ray + 2] = b * inv;
}

// ---------------------------------------------------------------------------
// Launch. Inputs (metadata order): rays_o[4096*3], rays_d[4096*3],
// xyz[100000*3], features_dc[100000*1*3], opacity[100000*1]. Output f32 [4096*3].
// ---------------------------------------------------------------------------
extern "C" void kernel_launch(void* const* d_in, const int* in_sizes, int n_in,
                              void* d_out, int out_size) {
    const float* rays_o      = (const float*)d_in[0];
    const float* rays_d      = (const float*)d_in[1];
    const float* xyz         = (const float*)d_in[2];
    const float* features_dc = (const float*)d_in[3];
    const float* opacity     = (const float*)d_in[4];
    float* out = (float*)d_out;

    prep_kernel<<<(NPAD + 255) / 256, 256>>>(xyz);

    dim3 grid(NGROUP / GROUPS_PER_BLOCK, NCHUNK);  // (16, 16)
    scan_kernel<<<grid, GROUPS_PER_BLOCK * 32>>>(rays_o, rays_d);

    merge_kernel<<<(BATCH + 255) / 256, 256>>>(rays_o, rays_d, features_dc, opacity, out);
}

// round 3
// speedup vs baseline: 2.2968x; 2.2968x over previous
#include <cuda_runtime.h>
#include <math_constants.h>

// Problem constants
#define NPTS   100000
#define BATCH  4096
#define TOPK   10

// Tiling
#define NCHUNK 32                  // point chunks for the scan
#define PC     3136                // points per chunk (mult of 8); NCHUNK*PC = 100352
#define NPAD   (NCHUNK * PC)
#define NPAIR  (NPAD / 2)
#define NGROUP 128                 // ray groups of 32 (NGROUP*32 = BATCH)
#define GPB    8                   // warps per block (scan)
#define CAP    128                 // candidate capacity per (ray, chunk)

#define NSAMP      4096            // prepass sample = first 4096 points
#define SAMP_ITERS 64              // pair-iterations per lane (64*32 lanes*2 pts = 4096)

// ---------------------------------------------------------------------------
// Device scratch (no allocation allowed)
// ---------------------------------------------------------------------------
__device__ float4 g_xy[NPAIR];             // (x0, x1, y0, y1) per point pair
__device__ float4 g_zw[NPAIR];             // (z0, z1, w0, w1), w = |p|^2 (pad: +INF)
__device__ float  g_tau[BATCH];            // per-ray threshold (already bumped up)
__device__ float2 g_buf[BATCH * NCHUNK * CAP];  // (t, idx-bits) candidates
__device__ int    g_cnt[BATCH * NCHUNK];

// ---------------------------------------------------------------------------
// f32x2 packed helpers
// ---------------------------------------------------------------------------
__device__ __forceinline__ unsigned long long pack2(float a, float b) {
    unsigned long long r;
    asm("mov.b64 %0, {%1, %2};" : "=l"(r) : "f"(a), "f"(b));
    return r;
}
__device__ __forceinline__ void unpack2(unsigned long long v, float& lo, float& hi) {
    asm("mov.b64 {%0, %1}, %2;" : "=f"(lo), "=f"(hi) : "l"(v));
}
__device__ __forceinline__ unsigned long long fma2(unsigned long long a,
                                                   unsigned long long b,
                                                   unsigned long long c) {
    unsigned long long d;
    asm("fma.rn.f32x2 %0, %1, %2, %3;" : "=l"(d) : "l"(a), "l"(b), "l"(c));
    return d;
}

// Identical t-chain used by BOTH prepass and scan (bit-exact per point):
// t = x*mx + (y*my + (z*mz + w))
__device__ __forceinline__ unsigned long long t_chain(
    unsigned long long xx, unsigned long long yy,
    unsigned long long zz, unsigned long long ww,
    unsigned long long mx2, unsigned long long my2, unsigned long long mz2) {
    return fma2(xx, mx2, fma2(yy, my2, fma2(zz, mz2, ww)));
}

// Bump a float up by a few ulps (so strict < passes for t <= tau)
__device__ __forceinline__ float bump_up(float x) {
    unsigned u = __float_as_uint(x);
    if (x > 0.0f)      { u += 8; }
    else if (x < 0.0f) { if ((u & 0x7FFFFFFFu) <= 8u) return 1e-30f; u -= 8; }
    else               { return 1e-30f; }
    return __uint_as_float(u);
}

// Ray center helpers
__device__ __forceinline__ void ray_center(const float* ro, const float* rd, int ray,
                                           float& cx, float& cy, float& cz) {
    cx = fmaf(3.0f, rd[3 * ray + 0], ro[3 * ray + 0]);
    cy = fmaf(3.0f, rd[3 * ray + 1], ro[3 * ray + 1]);
    cz = fmaf(3.0f, rd[3 * ray + 2], ro[3 * ray + 2]);
}

// ---------------------------------------------------------------------------
// Prep: build pair-packed point arrays with precomputed |p|^2 (pad w=+INF)
// ---------------------------------------------------------------------------
__global__ void prep_kernel(const float* __restrict__ xyz) {
    int q = blockIdx.x * blockDim.x + threadIdx.x;   // pair index
    if (q >= NPAIR) return;
    float v[2][4];
#pragma unroll
    for (int s = 0; s < 2; ++s) {
        int i = 2 * q + s;
        if (i < NPTS) {
            float x = xyz[3 * i + 0], y = xyz[3 * i + 1], z = xyz[3 * i + 2];
            v[s][0] = x; v[s][1] = y; v[s][2] = z;
            v[s][3] = fmaf(x, x, fmaf(y, y, z * z));
        } else {
            v[s][0] = 0.f; v[s][1] = 0.f; v[s][2] = 0.f; v[s][3] = CUDART_INF_F;
        }
    }
    g_xy[q] = make_float4(v[0][0], v[1][0], v[0][1], v[1][1]);
    g_zw[q] = make_float4(v[0][2], v[1][2], v[0][3], v[1][3]);
}

// ---------------------------------------------------------------------------
// Tau prepass: warp per ray. Lanes stream 4096 sample points keeping 4 min
// accumulators each (128 subset-minima / ray). tau = 10th smallest of the
// 128 minima  (subset 10th >= full-set 10th: always a SOUND threshold).
// ---------------------------------------------------------------------------
__global__ void __launch_bounds__(256)
tau_kernel(const float* __restrict__ rays_o, const float* __restrict__ rays_d) {
    const int warp = threadIdx.x >> 5;
    const int lane = threadIdx.x & 31;
    const int ray  = blockIdx.x * (blockDim.x >> 5) + warp;

    __shared__ float s_min[8][128];

    float cx, cy, cz;
    ray_center(rays_o, rays_d, ray, cx, cy, cz);
    const unsigned long long mx2 = pack2(-2.0f * cx, -2.0f * cx);
    const unsigned long long my2 = pack2(-2.0f * cy, -2.0f * cy);
    const unsigned long long mz2 = pack2(-2.0f * cz, -2.0f * cz);

    const ulonglong2* __restrict__ xy = reinterpret_cast<const ulonglong2*>(g_xy);
    const ulonglong2* __restrict__ zw = reinterpret_cast<const ulonglong2*>(g_zw);

    float a0 = CUDART_INF_F, a1 = CUDART_INF_F, a2 = CUDART_INF_F, a3 = CUDART_INF_F;

#pragma unroll 4
    for (int it = 0; it < SAMP_ITERS; it += 2) {
        {
            int q = it * 32 + lane;
            ulonglong2 pxy = xy[q], pzw = zw[q];
            float lo, hi;
            unpack2(t_chain(pxy.x, pxy.y, pzw.x, pzw.y, mx2, my2, mz2), lo, hi);
            a0 = fminf(a0, lo); a1 = fminf(a1, hi);
        }
        {
            int q = (it + 1) * 32 + lane;
            ulonglong2 pxy = xy[q], pzw = zw[q];
            float lo, hi;
            unpack2(t_chain(pxy.x, pxy.y, pzw.x, pzw.y, mx2, my2, mz2), lo, hi);
            a2 = fminf(a2, lo); a3 = fminf(a3, hi);
        }
    }

    s_min[warp][lane * 4 + 0] = a0;
    s_min[warp][lane * 4 + 1] = a1;
    s_min[warp][lane * 4 + 2] = a2;
    s_min[warp][lane * 4 + 3] = a3;
    __syncwarp();

    if (lane == 0) {
        float best[TOPK];
#pragma unroll
        for (int j = 0; j < TOPK; ++j) best[j] = CUDART_INF_F;
        for (int j = 0; j < 128; ++j) {
            float v = s_min[warp][j];
            if (v < best[TOPK - 1]) {
                int k = TOPK - 1;
#pragma unroll
                for (int s = TOPK - 1; s > 0; --s) {
                    if (v < best[s - 1]) { best[s] = best[s - 1]; k = s - 1; }
                }
                best[k] = v;
            }
        }
        g_tau[ray] = bump_up(best[TOPK - 1]);
    }
}

// ---------------------------------------------------------------------------
// Scan: warp = 32 rays (lane per ray), each warp filters one point chunk
// against the FIXED per-ray threshold tau. No top-K state in the loop.
// Qualifying (t, idx) append to a private per-(ray,chunk) buffer.
// ---------------------------------------------------------------------------
__global__ void __launch_bounds__(GPB * 32)
scan_kernel(const float* __restrict__ rays_o, const float* __restrict__ rays_d) {
    const int warp  = threadIdx.x >> 5;
    const int lane  = threadIdx.x & 31;
    const int group = blockIdx.x * GPB + warp;   // [0, NGROUP)
    const int chunk = blockIdx.y;                 // [0, NCHUNK)
    const int ray   = group * 32 + lane;

    float cx, cy, cz;
    ray_center(rays_o, rays_d, ray, cx, cy, cz);
    const unsigned long long mx2 = pack2(-2.0f * cx, -2.0f * cx);
    const unsigned long long my2 = pack2(-2.0f * cy, -2.0f * cy);
    const unsigned long long mz2 = pack2(-2.0f * cz, -2.0f * cz);
    const float thr = g_tau[ray];

    const ulonglong2* __restrict__ xy = reinterpret_cast<const ulonglong2*>(g_xy);
    const ulonglong2* __restrict__ zw = reinterpret_cast<const ulonglong2*>(g_zw);

    float2* __restrict__ buf = g_buf + (ray * NCHUNK + chunk) * CAP;
    int cnt = 0;

    const int q0 = chunk * (PC / 2);

#pragma unroll 2
    for (int g = 0; g < PC / 8; ++g) {
        const int q = q0 + g * 4;
        ulonglong2 xy0 = xy[q + 0], zw0 = zw[q + 0];
        ulonglong2 xy1 = xy[q + 1], zw1 = zw[q + 1];
        ulonglong2 xy2 = xy[q + 2], zw2 = zw[q + 2];
        ulonglong2 xy3 = xy[q + 3], zw3 = zw[q + 3];

        float l0, h0, l1, h1, l2, h2, l3, h3;
        unpack2(t_chain(xy0.x, xy0.y, zw0.x, zw0.y, mx2, my2, mz2), l0, h0);
        unpack2(t_chain(xy1.x, xy1.y, zw1.x, zw1.y, mx2, my2, mz2), l1, h1);
        unpack2(t_chain(xy2.x, xy2.y, zw2.x, zw2.y, mx2, my2, mz2), l2, h2);
        unpack2(t_chain(xy3.x, xy3.y, zw3.x, zw3.y, mx2, my2, mz2), l3, h3);

        float m = fminf(fminf(fminf(l0, h0), fminf(l1, h1)),
                        fminf(fminf(l2, h2), fminf(l3, h3)));
        if (m < thr) {
            const int base_idx = 2 * q;
            if (l0 < thr && cnt < CAP) { buf[cnt] = make_float2(l0, __int_as_float(base_idx + 0)); cnt++; }
            if (h0 < thr && cnt < CAP) { buf[cnt] = make_float2(h0, __int_as_float(base_idx + 1)); cnt++; }
            if (l1 < thr && cnt < CAP) { buf[cnt] = make_float2(l1, __int_as_float(base_idx + 2)); cnt++; }
            if (h1 < thr && cnt < CAP) { buf[cnt] = make_float2(h1, __int_as_float(base_idx + 3)); cnt++; }
            if (l2 < thr && cnt < CAP) { buf[cnt] = make_float2(l2, __int_as_float(base_idx + 4)); cnt++; }
            if (h2 < thr && cnt < CAP) { buf[cnt] = make_float2(h2, __int_as_float(base_idx + 5)); cnt++; }
            if (l3 < thr && cnt < CAP) { buf[cnt] = make_float2(l3, __int_as_float(base_idx + 6)); cnt++; }
            if (h3 < thr && cnt < CAP) { buf[cnt] = make_float2(h3, __int_as_float(base_idx + 7)); cnt++; }
        }
    }

    g_cnt[ray * NCHUNK + chunk] = cnt;
}

// ---------------------------------------------------------------------------
// Merge: thread per ray. Exact top-10 over ~270 candidates + epilogue.
// Candidates are in (chunk, index) order -> lowest-index tie stability.
// ---------------------------------------------------------------------------
__global__ void __launch_bounds__(256)
merge_kernel(const float* __restrict__ rays_o, const float* __restrict__ rays_d,
             const float* __restrict__ features_dc, const float* __restrict__ opacity,
             float* __restrict__ out) {
    const int ray = blockIdx.x * blockDim.x + threadIdx.x;
    if (ray >= BATCH) return;

    float d[TOPK];
    int   id[TOPK];
#pragma unroll
    for (int j = 0; j < TOPK; ++j) { d[j] = CUDART_INF_F; id[j] = 0; }

    for (int c = 0; c < NCHUNK; ++c) {
        int n = g_cnt[ray * NCHUNK + c];
        n = n < CAP ? n : CAP;
        const float2* __restrict__ buf = g_buf + (ray * NCHUNK + c) * CAP;
        for (int j = 0; j < n; ++j) {
            float2 e = buf[j];
            float t = e.x;
            if (t < d[TOPK - 1]) {
                int i = __float_as_int(e.y);
                // sorted shift insert (strict < keeps earlier = lower index)
                int pos = TOPK - 1;
#pragma unroll
                for (int s = TOPK - 1; s > 0; --s) {
                    if (t < d[s - 1]) { d[s] = d[s - 1]; id[s] = id[s - 1]; pos = s - 1; }
                }
                d[pos] = t; id[pos] = i;
            }
        }
    }

    float cx, cy, cz;
    ray_center(rays_o, rays_d, ray, cx, cy, cz);
    const float c2 = fmaf(cx, cx, fmaf(cy, cy, cz * cz));

    float wsum = 0.0f, r = 0.0f, g = 0.0f, b = 0.0f;
#pragma unroll
    for (int j = 0; j < TOPK; ++j) {
        const int   k    = id[j];
        const float sq   = fmaxf(d[j] + c2, 0.0f);
        const float dist = sqrtf(sq);
        const float op   = 1.0f / (1.0f + expf(-opacity[k]));
        const float w    = expf(-0.1f * dist) * op;
        wsum += w;
        r = fmaf(w, 1.0f / (1.0f + expf(-features_dc[3 * k + 0])), r);
        g = fmaf(w, 1.0f / (1.0f + expf(-features_dc[3 * k + 1])), g);
        b = fmaf(w, 1.0f / (1.0f + expf(-features_dc[3 * k + 2])), b);
    }
    const float inv = 1.0f / (wsum + 1e-8f);
    out[3 * ray + 0] = r * inv;
    out[3 * ray + 1] = g * inv;
    out[3 * ray + 2] = b * inv;
}

// ---------------------------------------------------------------------------
// Launch. Inputs: rays_o, rays_d, xyz, features_dc, opacity. Output f32 [B,3].
// ---------------------------------------------------------------------------
extern "C" void kernel_launch(void* const* d_in, const int* in_sizes, int n_in,
                              void* d_out, int out_size) {
    const float* rays_o      = (const float*)d_in[0];
    const float* rays_d      = (const float*)d_in[1];
    const float* xyz         = (const float*)d_in[2];
    const float* features_dc = (const float*)d_in[3];
    const float* opacity     = (const float*)d_in[4];
    float* out = (float*)d_out;

    prep_kernel<<<(NPAIR + 255) / 256, 256>>>(xyz);

    tau_kernel<<<BATCH / 8, 256>>>(rays_o, rays_d);   // warp per ray

    dim3 grid(NGROUP / GPB, NCHUNK);                  // (16, 32)
    scan_kernel<<<grid, GPB * 32>>>(rays_o, rays_d);

    merge_kernel<<<(BATCH + 255) / 256, 256>>>(rays_o, rays_d, features_dc, opacity, out);
}

// round 4
// speedup vs baseline: 5.1213x; 2.2298x over previous
#include <cuda_runtime.h>
#include <math_constants.h>

// Problem constants
#define NPTS   100000
#define BATCH  4096
#define TOPK   10

// Tiling
#define NCHUNK 32                  // point chunks (== warp lanes in merge)
#define PC     3328                // points per chunk = 13 tiles * 256 pts
#define NPAD   (NCHUNK * PC)       // 106496
#define NPAIR  (NPAD / 2)          // 53248
#define PAIRS_PER_CHUNK (PC / 2)   // 1664
#define TILE_PAIRS 128             // pairs staged per smem tile (4KB)
#define NTILES (PAIRS_PER_CHUNK / TILE_PAIRS)  // 13
#define NGROUP 128                 // ray groups of 32 (NGROUP*32 = BATCH)
#define GPB    8                   // warps per block (scan)
#define CAP    128                 // candidate capacity per (ray, chunk)

#define SAMP_ITERS 64              // tau prepass: 64*32 lanes*2 pts = 4096 samples

// ---------------------------------------------------------------------------
// Device scratch (static; no runtime allocation)
// ---------------------------------------------------------------------------
__device__ float4 g_xy[NPAIR];             // (x0, x1, y0, y1) per point pair
__device__ float4 g_zw[NPAIR];             // (z0, z1, w0, w1), w=|p|^2 (pad +INF)
__device__ float  g_tau[BATCH];            // per-ray threshold (pre-bumped)
__device__ float2 g_buf[BATCH * NCHUNK * CAP];  // (t, idx-bits)
__device__ int    g_cnt[BATCH * NCHUNK];

// ---------------------------------------------------------------------------
// f32x2 packed helpers
// ---------------------------------------------------------------------------
__device__ __forceinline__ unsigned long long pack2(float a, float b) {
    unsigned long long r;
    asm("mov.b64 %0, {%1, %2};" : "=l"(r) : "f"(a), "f"(b));
    return r;
}
__device__ __forceinline__ void unpack2(unsigned long long v, float& lo, float& hi) {
    asm("mov.b64 {%0, %1}, %2;" : "=f"(lo), "=f"(hi) : "l"(v));
}
__device__ __forceinline__ unsigned long long fma2(unsigned long long a,
                                                   unsigned long long b,
                                                   unsigned long long c) {
    unsigned long long d;
    asm("fma.rn.f32x2 %0, %1, %2, %3;" : "=l"(d) : "l"(a), "l"(b), "l"(c));
    return d;
}
// Identical per-point chain everywhere (bit-exact): t = x*mx + (y*my + (z*mz + w))
__device__ __forceinline__ unsigned long long t_chain(
    unsigned long long xx, unsigned long long yy,
    unsigned long long zz, unsigned long long ww,
    unsigned long long mx2, unsigned long long my2, unsigned long long mz2) {
    return fma2(xx, mx2, fma2(yy, my2, fma2(zz, mz2, ww)));
}

__device__ __forceinline__ float bump_up(float x) {
    unsigned u = __float_as_uint(x);
    if (x > 0.0f)      { u += 8; }
    else if (x < 0.0f) { if ((u & 0x7FFFFFFFu) <= 8u) return 1e-30f; u -= 8; }
    else               { return 1e-30f; }
    return __uint_as_float(u);
}

__device__ __forceinline__ void ray_center(const float* ro, const float* rd, int ray,
                                           float& cx, float& cy, float& cz) {
    cx = fmaf(3.0f, rd[3 * ray + 0], ro[3 * ray + 0]);
    cy = fmaf(3.0f, rd[3 * ray + 1], ro[3 * ray + 1]);
    cz = fmaf(3.0f, rd[3 * ray + 2], ro[3 * ray + 2]);
}

// Monotone float -> uint32 (order-preserving over all finite + inf values)
__device__ __forceinline__ unsigned f2sort(float f) {
    unsigned u = __float_as_uint(f);
    return ((int)u < 0) ? ~u : (u | 0x80000000u);
}
__device__ __forceinline__ float sort2f(unsigned s) {
    return (s & 0x80000000u) ? __uint_as_float(s ^ 0x80000000u)
                             : __uint_as_float(~s);
}

// ---------------------------------------------------------------------------
// Prep: pair-packed point arrays with |p|^2 (pad w=+INF)
// ---------------------------------------------------------------------------
__global__ void prep_kernel(const float* __restrict__ xyz) {
    int q = blockIdx.x * blockDim.x + threadIdx.x;
    if (q >= NPAIR) return;
    float v[2][4];
#pragma unroll
    for (int s = 0; s < 2; ++s) {
        int i = 2 * q + s;
        if (i < NPTS) {
            float x = xyz[3 * i + 0], y = xyz[3 * i + 1], z = xyz[3 * i + 2];
            v[s][0] = x; v[s][1] = y; v[s][2] = z;
            v[s][3] = fmaf(x, x, fmaf(y, y, z * z));
        } else {
            v[s][0] = 0.f; v[s][1] = 0.f; v[s][2] = 0.f; v[s][3] = CUDART_INF_F;
        }
    }
    g_xy[q] = make_float4(v[0][0], v[1][0], v[0][1], v[1][1]);
    g_zw[q] = make_float4(v[0][2], v[1][2], v[0][3], v[1][3]);
}

// ---------------------------------------------------------------------------
// Tau prepass: warp per ray over first 4096 points; tau = 10th smallest of
// 128 subset-minima (always >= true 10th smallest: sound threshold).
// ---------------------------------------------------------------------------
__global__ void __launch_bounds__(256)
tau_kernel(const float* __restrict__ rays_o, const float* __restrict__ rays_d) {
    const int warp = threadIdx.x >> 5;
    const int lane = threadIdx.x & 31;
    const int ray  = blockIdx.x * (blockDim.x >> 5) + warp;

    __shared__ float s_min[8][128];

    float cx, cy, cz;
    ray_center(rays_o, rays_d, ray, cx, cy, cz);
    const unsigned long long mx2 = pack2(-2.0f * cx, -2.0f * cx);
    const unsigned long long my2 = pack2(-2.0f * cy, -2.0f * cy);
    const unsigned long long mz2 = pack2(-2.0f * cz, -2.0f * cz);

    const ulonglong2* __restrict__ xy = reinterpret_cast<const ulonglong2*>(g_xy);
    const ulonglong2* __restrict__ zw = reinterpret_cast<const ulonglong2*>(g_zw);

    float a0 = CUDART_INF_F, a1 = CUDART_INF_F, a2 = CUDART_INF_F, a3 = CUDART_INF_F;

#pragma unroll 4
    for (int it = 0; it < SAMP_ITERS; it += 2) {
        {
            int q = it * 32 + lane;
            ulonglong2 pxy = xy[q], pzw = zw[q];
            float lo, hi;
            unpack2(t_chain(pxy.x, pxy.y, pzw.x, pzw.y, mx2, my2, mz2), lo, hi);
            a0 = fminf(a0, lo); a1 = fminf(a1, hi);
        }
        {
            int q = (it + 1) * 32 + lane;
            ulonglong2 pxy = xy[q], pzw = zw[q];
            float lo, hi;
            unpack2(t_chain(pxy.x, pxy.y, pzw.x, pzw.y, mx2, my2, mz2), lo, hi);
            a2 = fminf(a2, lo); a3 = fminf(a3, hi);
        }
    }

    s_min[warp][lane * 4 + 0] = a0;
    s_min[warp][lane * 4 + 1] = a1;
    s_min[warp][lane * 4 + 2] = a2;
    s_min[warp][lane * 4 + 3] = a3;
    __syncwarp();

    if (lane == 0) {
        float best[TOPK];
#pragma unroll
        for (int j = 0; j < TOPK; ++j) best[j] = CUDART_INF_F;
        for (int j = 0; j < 128; ++j) {
            float v = s_min[warp][j];
            if (v < best[TOPK - 1]) {
                int k = TOPK - 1;
#pragma unroll
                for (int s = TOPK - 1; s > 0; --s) {
                    if (v < best[s - 1]) { best[s] = best[s - 1]; k = s - 1; }
                }
                best[k] = v;
            }
        }
        g_tau[ray] = bump_up(best[TOPK - 1]);
    }
}

// ---------------------------------------------------------------------------
// Scan: block = 8 warps, all scanning the SAME chunk (blockIdx.y) for 8
// different ray groups. Points staged tile-by-tile into shared memory once
// per block; warps read via uniform-broadcast LDS. Warp-coherent rare-path
// branch via __any_sync. Appends (t, idx) under fixed per-ray tau.
// ---------------------------------------------------------------------------
__global__ void __launch_bounds__(GPB * 32)
scan_kernel(const float* __restrict__ rays_o, const float* __restrict__ rays_d) {
    const int warp  = threadIdx.x >> 5;
    const int lane  = threadIdx.x & 31;
    const int group = blockIdx.x * GPB + warp;
    const int chunk = blockIdx.y;
    const int ray   = group * 32 + lane;

    __shared__ float4 s_xy[TILE_PAIRS];
    __shared__ float4 s_zw[TILE_PAIRS];

    float cx, cy, cz;
    ray_center(rays_o, rays_d, ray, cx, cy, cz);
    const unsigned long long mx2 = pack2(-2.0f * cx, -2.0f * cx);
    const unsigned long long my2 = pack2(-2.0f * cy, -2.0f * cy);
    const unsigned long long mz2 = pack2(-2.0f * cz, -2.0f * cz);
    const float thr = g_tau[ray];

    float2* __restrict__ buf = g_buf + (ray * NCHUNK + chunk) * CAP;
    int cnt = 0;

    const int chunk_pair0 = chunk * PAIRS_PER_CHUNK;
    const ulonglong2* __restrict__ sxy = reinterpret_cast<const ulonglong2*>(s_xy);
    const ulonglong2* __restrict__ szw = reinterpret_cast<const ulonglong2*>(s_zw);

    for (int tile = 0; tile < NTILES; ++tile) {
        // Stage 128 pairs (256 points, 4KB) cooperatively
        {
            const int t = threadIdx.x;
            const int src = chunk_pair0 + tile * TILE_PAIRS;
            if (t < TILE_PAIRS)       s_xy[t]              = g_xy[src + t];
            else                      s_zw[t - TILE_PAIRS] = g_zw[src + (t - TILE_PAIRS)];
        }
        __syncthreads();

#pragma unroll 2
        for (int g = 0; g < TILE_PAIRS / 4; ++g) {
            const int q = g * 4;
            ulonglong2 xy0 = sxy[q + 0], zw0 = szw[q + 0];
            ulonglong2 xy1 = sxy[q + 1], zw1 = szw[q + 1];
            ulonglong2 xy2 = sxy[q + 2], zw2 = szw[q + 2];
            ulonglong2 xy3 = sxy[q + 3], zw3 = szw[q + 3];

            float l0, h0, l1, h1, l2, h2, l3, h3;
            unpack2(t_chain(xy0.x, xy0.y, zw0.x, zw0.y, mx2, my2, mz2), l0, h0);
            unpack2(t_chain(xy1.x, xy1.y, zw1.x, zw1.y, mx2, my2, mz2), l1, h1);
            unpack2(t_chain(xy2.x, xy2.y, zw2.x, zw2.y, mx2, my2, mz2), l2, h2);
            unpack2(t_chain(xy3.x, xy3.y, zw3.x, zw3.y, mx2, my2, mz2), l3, h3);

            float m = fminf(fminf(fminf(l0, h0), fminf(l1, h1)),
                            fminf(fminf(l2, h2), fminf(l3, h3)));
            if (__any_sync(0xFFFFFFFFu, m < thr)) {
                const int base_idx = 2 * (chunk_pair0 + tile * TILE_PAIRS + q);
                if (l0 < thr && cnt < CAP) { buf[cnt] = make_float2(l0, __int_as_float(base_idx + 0)); cnt++; }
                if (h0 < thr && cnt < CAP) { buf[cnt] = make_float2(h0, __int_as_float(base_idx + 1)); cnt++; }
                if (l1 < thr && cnt < CAP) { buf[cnt] = make_float2(l1, __int_as_float(base_idx + 2)); cnt++; }
                if (h1 < thr && cnt < CAP) { buf[cnt] = make_float2(h1, __int_as_float(base_idx + 3)); cnt++; }
                if (l2 < thr && cnt < CAP) { buf[cnt] = make_float2(l2, __int_as_float(base_idx + 4)); cnt++; }
                if (h2 < thr && cnt < CAP) { buf[cnt] = make_float2(h2, __int_as_float(base_idx + 5)); cnt++; }
                if (l3 < thr && cnt < CAP) { buf[cnt] = make_float2(l3, __int_as_float(base_idx + 6)); cnt++; }
                if (h3 < thr && cnt < CAP) { buf[cnt] = make_float2(h3, __int_as_float(base_idx + 7)); cnt++; }
            }
        }
        __syncthreads();
    }

    g_cnt[ray * NCHUNK + chunk] = cnt;
}

// ---------------------------------------------------------------------------
// Merge: WARP per ray. Lane = chunk. Each lane builds a local sorted top-10
// of its chunk's candidates; 10 rounds of warp-wide 64-bit min-reduce over
// (sortable(t)<<32 | idx) select the global top-10 with exact stable
// tie-breaking (lowest index). Epilogue distributed over lanes 0..9.
// ---------------------------------------------------------------------------
__global__ void __launch_bounds__(256)
merge_kernel(const float* __restrict__ rays_o, const float* __restrict__ rays_d,
             const float* __restrict__ features_dc, const float* __restrict__ opacity,
             float* __restrict__ out) {
    const int warp = threadIdx.x >> 5;
    const int lane = threadIdx.x & 31;
    const int ray  = blockIdx.x * (blockDim.x >> 5) + warp;

    // Per-lane local top-10 of this lane's chunk
    float d[TOPK];
    int   id[TOPK];
#pragma unroll
    for (int j = 0; j < TOPK; ++j) { d[j] = CUDART_INF_F; id[j] = 0; }

    {
        int n = g_cnt[ray * NCHUNK + lane];
        n = n < CAP ? n : CAP;
        const float2* __restrict__ buf = g_buf + (ray * NCHUNK + lane) * CAP;
        for (int j = 0; j < n; ++j) {
            float2 e = buf[j];
            float t = e.x;
            if (t < d[TOPK - 1]) {
                int i = __float_as_int(e.y);
                int pos = TOPK - 1;
#pragma unroll
                for (int s = TOPK - 1; s > 0; --s) {
                    if (t < d[s - 1]) { d[s] = d[s - 1]; id[s] = id[s - 1]; pos = s - 1; }
                }
                d[pos] = t; id[pos] = i;
            }
        }
    }

    // 10 rounds of warp min selection over per-lane list heads
    int h = 0;
    unsigned long long cur =
        ((unsigned long long)f2sort(d[0]) << 32) | (unsigned)id[0];
    unsigned long long sel = 0xFFFFFFFFFFFFFFFFull;  // this lane's selected entry

#pragma unroll
    for (int r = 0; r < TOPK; ++r) {
        unsigned long long k = cur;
#pragma unroll
        for (int off = 16; off > 0; off >>= 1) {
            unsigned long long o = __shfl_xor_sync(0xFFFFFFFFu, k, off);
            k = o < k ? o : k;
        }
        // k = global min this round (broadcast to all lanes)
        if (lane == r) sel = k;
        if (cur == k) {  // owner pops (keys unique: idx distinct)
            ++h;
            cur = (h < TOPK)
                ? (((unsigned long long)f2sort(d[h]) << 32) | (unsigned)id[h])
                : 0xFFFFFFFFFFFFFFFFull;
        }
    }

    // Epilogue: lanes 0..9 each handle one selected neighbor
    float cx, cy, cz;
    ray_center(rays_o, rays_d, ray, cx, cy, cz);
    const float c2 = fmaf(cx, cx, fmaf(cy, cy, cz * cz));

    float w = 0.f, wr = 0.f, wg = 0.f, wb = 0.f;
    if (lane < TOPK) {
        const int   k    = (int)(unsigned)sel;
        const float t    = sort2f((unsigned)(sel >> 32));
        const float sq   = fmaxf(t + c2, 0.0f);
        const float dist = sqrtf(sq);
        const float op   = 1.0f / (1.0f + expf(-opacity[k]));
        w = expf(-0.1f * dist) * op;
        wr = w * (1.0f / (1.0f + expf(-features_dc[3 * k + 0])));
        wg = w * (1.0f / (1.0f + expf(-features_dc[3 * k + 1])));
        wb = w * (1.0f / (1.0f + expf(-features_dc[3 * k + 2])));
    }
#pragma unroll
    for (int off = 16; off > 0; off >>= 1) {
        w  += __shfl_xor_sync(0xFFFFFFFFu, w,  off);
        wr += __shfl_xor_sync(0xFFFFFFFFu, wr, off);
        wg += __shfl_xor_sync(0xFFFFFFFFu, wg, off);
        wb += __shfl_xor_sync(0xFFFFFFFFu, wb, off);
    }
    if (lane == 0) {
        const float inv = 1.0f / (w + 1e-8f);
        out[3 * ray + 0] = wr * inv;
        out[3 * ray + 1] = wg * inv;
        out[3 * ray + 2] = wb * inv;
    }
}

// ---------------------------------------------------------------------------
// Launch
// ---------------------------------------------------------------------------
extern "C" void kernel_launch(void* const* d_in, const int* in_sizes, int n_in,
                              void* d_out, int out_size) {
    const float* rays_o      = (const float*)d_in[0];
    const float* rays_d      = (const float*)d_in[1];
    const float* xyz         = (const float*)d_in[2];
    const float* features_dc = (const float*)d_in[3];
    const float* opacity     = (const float*)d_in[4];
    float* out = (float*)d_out;

    prep_kernel<<<(NPAIR + 255) / 256, 256>>>(xyz);

    tau_kernel<<<BATCH / 8, 256>>>(rays_o, rays_d);       // warp per ray

    dim3 grid(NGROUP / GPB, NCHUNK);                      // (16, 32)
    scan_kernel<<<grid, GPB * 32>>>(rays_o, rays_d);

    merge_kernel<<<BATCH / 8, 256>>>(rays_o, rays_d, features_dc, opacity, out);
}

// round 6
// speedup vs baseline: 5.9057x; 1.1532x over previous
#include <cuda_runtime.h>
#include <math_constants.h>

// Problem constants
#define NPTS   100000
#define BATCH  4096
#define TOPK   10

// Scan tiling
#define NCHUNK 32                  // point chunks (== warp lanes in merge)
#define PC     3328                // points per chunk = 13 tiles * 256 pts
#define NPAD   (NCHUNK * PC)       // 106496
#define NPAIR  (NPAD / 2)          // 53248
#define PAIRS_PER_CHUNK (PC / 2)   // 1664
#define TILE_PAIRS 128             // pairs staged per smem tile (4KB)
#define NTILES (PAIRS_PER_CHUNK / TILE_PAIRS)  // 13
#define NGROUP 128                 // ray groups of 32 (NGROUP*32 = BATCH)
#define GPB    8                   // warps per block
#define CAP    32                  // candidate capacity per (ray, chunk)

// Tau prepass tiling: 16384 sample points = 8192 pairs, 8 sample-chunks
#define NTAUCH       8
#define SCHUNK_PAIRS 1024          // pairs per sample chunk
#define NACC         2             // min-accumulators per lane per chunk
#define NMINS        (NTAUCH * NACC)   // 16 block-minima per ray

// ---------------------------------------------------------------------------
// Device scratch (static; no runtime allocation)
// ---------------------------------------------------------------------------
__device__ float4 g_xy[NPAIR];               // (x0, x1, y0, y1) per point pair
__device__ float4 g_zw[NPAIR];               // (z0, z1, w0, w1), w=|p|^2 (pad +INF)
__device__ float  g_pmin[NMINS * BATCH];     // per-ray block minima
__device__ float  g_tau[BATCH];              // per-ray threshold (pre-bumped)
__device__ float2 g_buf[BATCH * NCHUNK * CAP];  // (t, idx-bits)
__device__ int    g_cnt[BATCH * NCHUNK];

// ---------------------------------------------------------------------------
// f32x2 packed helpers
// ---------------------------------------------------------------------------
__device__ __forceinline__ unsigned long long pack2(float a, float b) {
    unsigned long long r;
    asm("mov.b64 %0, {%1, %2};" : "=l"(r) : "f"(a), "f"(b));
    return r;
}
__device__ __forceinline__ void unpack2(unsigned long long v, float& lo, float& hi) {
    asm("mov.b64 {%0, %1}, %2;" : "=f"(lo), "=f"(hi) : "l"(v));
}
__device__ __forceinline__ unsigned long long fma2(unsigned long long a,
                                                   unsigned long long b,
                                                   unsigned long long c) {
    unsigned long long d;
    asm("fma.rn.f32x2 %0, %1, %2, %3;" : "=l"(d) : "l"(a), "l"(b), "l"(c));
    return d;
}
// Identical per-point chain everywhere (bit-exact): t = x*mx + (y*my + (z*mz + w))
__device__ __forceinline__ unsigned long long t_chain(
    unsigned long long xx, unsigned long long yy,
    unsigned long long zz, unsigned long long ww,
    unsigned long long mx2, unsigned long long my2, unsigned long long mz2) {
    return fma2(xx, mx2, fma2(yy, my2, fma2(zz, mz2, ww)));
}

// cp.async helpers (LDGSTS)
__device__ __forceinline__ void cp_async16(void* smem_dst, const void* gmem_src) {
    unsigned saddr = (unsigned)__cvta_generic_to_shared(smem_dst);
    asm volatile("cp.async.cg.shared.global [%0], [%1], 16;" :: "r"(saddr), "l"(gmem_src));
}
__device__ __forceinline__ void cp_commit() {
    asm volatile("cp.async.commit_group;");
}
template <int N>
__device__ __forceinline__ void cp_wait() {
    asm volatile("cp.async.wait_group %0;" :: "n"(N));
}

__device__ __forceinline__ float bump_up(float x) {
    unsigned u = __float_as_uint(x);
    if (x > 0.0f)      { u += 8; }
    else if (x < 0.0f) { if ((u & 0x7FFFFFFFu) <= 8u) return 1e-30f; u -= 8; }
    else               { return 1e-30f; }
    return __uint_as_float(u);
}

__device__ __forceinline__ void ray_center(const float* ro, const float* rd, int ray,
                                           float& cx, float& cy, float& cz) {
    cx = fmaf(3.0f, rd[3 * ray + 0], ro[3 * ray + 0]);
    cy = fmaf(3.0f, rd[3 * ray + 1], ro[3 * ray + 1]);
    cz = fmaf(3.0f, rd[3 * ray + 2], ro[3 * ray + 2]);
}

// Monotone float <-> uint32 (order-preserving incl. +/-inf)
__device__ __forceinline__ unsigned f2sort(float f) {
    unsigned u = __float_as_uint(f);
    return ((int)u < 0) ? ~u : (u | 0x80000000u);
}
__device__ __forceinline__ float sort2f(unsigned s) {
    return (s & 0x80000000u) ? __uint_as_float(s ^ 0x80000000u)
                             : __uint_as_float(~s);
}

// ---------------------------------------------------------------------------
// Prep: pair-packed point arrays with |p|^2 (pad w=+INF)
// ---------------------------------------------------------------------------
__global__ void prep_kernel(const float* __restrict__ xyz) {
    int q = blockIdx.x * blockDim.x + threadIdx.x;
    if (q >= NPAIR) return;
    float v[2][4];
#pragma unroll
    for (int s = 0; s < 2; ++s) {
        int i = 2 * q + s;
        if (i < NPTS) {
            float x = xyz[3 * i + 0], y = xyz[3 * i + 1], z = xyz[3 * i + 2];
            v[s][0] = x; v[s][1] = y; v[s][2] = z;
            v[s][3] = fmaf(x, x, fmaf(y, y, z * z));
        } else {
            v[s][0] = 0.f; v[s][1] = 0.f; v[s][2] = 0.f; v[s][3] = CUDART_INF_F;
        }
    }
    g_xy[q] = make_float4(v[0][0], v[1][0], v[0][1], v[1][1]);
    g_zw[q] = make_float4(v[0][2], v[1][2], v[0][3], v[1][3]);
}

// ---------------------------------------------------------------------------
// Tau part 1: broadcast layout (warp = 32 rays). blockIdx.y = sample chunk.
// Each lane keeps NACC=2 running minima over its chunk's 2048 sample points.
// Writes block-minima to g_pmin (coalesced).
// ---------------------------------------------------------------------------
__global__ void __launch_bounds__(GPB * 32)
tau_part_kernel(const float* __restrict__ rays_o, const float* __restrict__ rays_d) {
    const int warp  = threadIdx.x >> 5;
    const int lane  = threadIdx.x & 31;
    const int group = blockIdx.x * GPB + warp;
    const int sch   = blockIdx.y;                 // sample chunk [0, NTAUCH)
    const int ray   = group * 32 + lane;

    __shared__ float4 s_xy[TILE_PAIRS];
    __shared__ float4 s_zw[TILE_PAIRS];

    float cx, cy, cz;
    ray_center(rays_o, rays_d, ray, cx, cy, cz);
    const unsigned long long mx2 = pack2(-2.0f * cx, -2.0f * cx);
    const unsigned long long my2 = pack2(-2.0f * cy, -2.0f * cy);
    const unsigned long long mz2 = pack2(-2.0f * cz, -2.0f * cz);

    const ulonglong2* __restrict__ sxy = reinterpret_cast<const ulonglong2*>(s_xy);
    const ulonglong2* __restrict__ szw = reinterpret_cast<const ulonglong2*>(s_zw);

    float a0 = CUDART_INF_F, a1 = CUDART_INF_F;
    const int pair0 = sch * SCHUNK_PAIRS;

    for (int tile = 0; tile < SCHUNK_PAIRS / TILE_PAIRS; ++tile) {
        {
            const int t = threadIdx.x;
            const int src = pair0 + tile * TILE_PAIRS;
            if (t < TILE_PAIRS)       s_xy[t]              = g_xy[src + t];
            else                      s_zw[t - TILE_PAIRS] = g_zw[src + (t - TILE_PAIRS)];
        }
        __syncthreads();

#pragma unroll 4
        for (int q = 0; q < TILE_PAIRS; ++q) {
            ulonglong2 pxy = sxy[q], pzw = szw[q];
            float lo, hi;
            unpack2(t_chain(pxy.x, pxy.y, pzw.x, pzw.y, mx2, my2, mz2), lo, hi);
            a0 = fminf(a0, lo);
            a1 = fminf(a1, hi);
        }
        __syncthreads();
    }

    g_pmin[(sch * NACC + 0) * BATCH + ray] = a0;
    g_pmin[(sch * NACC + 1) * BATCH + ray] = a1;
}

// ---------------------------------------------------------------------------
// Tau part 2: thread per ray. tau = 10th smallest of 16 block minima
// (always >= true 10th smallest overall: sound), bumped up a few ulps.
// ---------------------------------------------------------------------------
__global__ void __launch_bounds__(256)
tau_combine_kernel() {
    const int ray = blockIdx.x * blockDim.x + threadIdx.x;
    if (ray >= BATCH) return;
    float best[TOPK];
#pragma unroll
    for (int j = 0; j < TOPK; ++j) best[j] = CUDART_INF_F;
#pragma unroll
    for (int k = 0; k < NMINS; ++k) {
        float v = g_pmin[k * BATCH + ray];
        if (v < best[TOPK - 1]) {
            int pos = TOPK - 1;
#pragma unroll
            for (int s = TOPK - 1; s > 0; --s) {
                if (v < best[s - 1]) { best[s] = best[s - 1]; pos = s - 1; }
            }
            best[pos] = v;
        }
    }
    g_tau[ray] = bump_up(best[TOPK - 1]);
}

// ---------------------------------------------------------------------------
// Scan: block = 8 warps, all on chunk blockIdx.y for 8 ray groups. Point
// tiles double-buffered via cp.async; warps read via uniform-broadcast LDS.
// Appends (t, idx) under fixed per-ray tau; no top-K state in the loop.
// ---------------------------------------------------------------------------
__global__ void __launch_bounds__(GPB * 32)
scan_kernel(const float* __restrict__ rays_o, const float* __restrict__ rays_d) {
    const int warp  = threadIdx.x >> 5;
    const int lane  = threadIdx.x & 31;
    const int group = blockIdx.x * GPB + warp;
    const int chunk = blockIdx.y;
    const int ray   = group * 32 + lane;

    __shared__ float4 s_xy[2][TILE_PAIRS];
    __shared__ float4 s_zw[2][TILE_PAIRS];

    float cx, cy, cz;
    ray_center(rays_o, rays_d, ray, cx, cy, cz);
    const unsigned long long mx2 = pack2(-2.0f * cx, -2.0f * cx);
    const unsigned long long my2 = pack2(-2.0f * cy, -2.0f * cy);
    const unsigned long long mz2 = pack2(-2.0f * cz, -2.0f * cz);
    const float thr = g_tau[ray];

    float2* __restrict__ buf = g_buf + (ray * NCHUNK + chunk) * CAP;
    int cnt = 0;

    const int chunk_pair0 = chunk * PAIRS_PER_CHUNK;
    const int t = threadIdx.x;

    // Prefetch tile 0
    {
        const int src = chunk_pair0;
        if (t < TILE_PAIRS) cp_async16(&s_xy[0][t], &g_xy[src + t]);
        else                cp_async16(&s_zw[0][t - TILE_PAIRS], &g_zw[src + (t - TILE_PAIRS)]);
        cp_commit();
    }

    for (int tile = 0; tile < NTILES; ++tile) {
        const int cur = tile & 1;
        if (tile + 1 < NTILES) {
            const int nb  = (tile + 1) & 1;
            const int src = chunk_pair0 + (tile + 1) * TILE_PAIRS;
            if (t < TILE_PAIRS) cp_async16(&s_xy[nb][t], &g_xy[src + t]);
            else                cp_async16(&s_zw[nb][t - TILE_PAIRS], &g_zw[src + (t - TILE_PAIRS)]);
            cp_commit();
            cp_wait<1>();
        } else {
            cp_wait<0>();
        }
        __syncthreads();

        const ulonglong2* __restrict__ sxy = reinterpret_cast<const ulonglong2*>(s_xy[cur]);
        const ulonglong2* __restrict__ szw = reinterpret_cast<const ulonglong2*>(s_zw[cur]);

#pragma unroll 2
        for (int g = 0; g < TILE_PAIRS / 4; ++g) {
            const int q = g * 4;
            ulonglong2 xy0 = sxy[q + 0], zw0 = szw[q + 0];
            ulonglong2 xy1 = sxy[q + 1], zw1 = szw[q + 1];
            ulonglong2 xy2 = sxy[q + 2], zw2 = szw[q + 2];
            ulonglong2 xy3 = sxy[q + 3], zw3 = szw[q + 3];

            float l0, h0, l1, h1, l2, h2, l3, h3;
            unpack2(t_chain(xy0.x, xy0.y, zw0.x, zw0.y, mx2, my2, mz2), l0, h0);
            unpack2(t_chain(xy1.x, xy1.y, zw1.x, zw1.y, mx2, my2, mz2), l1, h1);
            unpack2(t_chain(xy2.x, xy2.y, zw2.x, zw2.y, mx2, my2, mz2), l2, h2);
            unpack2(t_chain(xy3.x, xy3.y, zw3.x, zw3.y, mx2, my2, mz2), l3, h3);

            float m = fminf(fminf(fminf(l0, h0), fminf(l1, h1)),
                            fminf(fminf(l2, h2), fminf(l3, h3)));
            if (__any_sync(0xFFFFFFFFu, m < thr)) {
                const int base_idx = 2 * (chunk_pair0 + tile * TILE_PAIRS + q);
                if (l0 < thr && cnt < CAP) { buf[cnt] = make_float2(l0, __int_as_float(base_idx + 0)); cnt++; }
                if (h0 < thr && cnt < CAP) { buf[cnt] = make_float2(h0, __int_as_float(base_idx + 1)); cnt++; }
                if (l1 < thr && cnt < CAP) { buf[cnt] = make_float2(l1, __int_as_float(base_idx + 2)); cnt++; }
                if (h1 < thr && cnt < CAP) { buf[cnt] = make_float2(h1, __int_as_float(base_idx + 3)); cnt++; }
                if (l2 < thr && cnt < CAP) { buf[cnt] = make_float2(l2, __int_as_float(base_idx + 4)); cnt++; }
                if (h2 < thr && cnt < CAP) { buf[cnt] = make_float2(h2, __int_as_float(base_idx + 5)); cnt++; }
                if (l3 < thr && cnt < CAP) { buf[cnt] = make_float2(l3, __int_as_float(base_idx + 6)); cnt++; }
                if (h3 < thr && cnt < CAP) { buf[cnt] = make_float2(h3, __int_as_float(base_idx + 7)); cnt++; }
            }
        }
        __syncthreads();
    }

    g_cnt[ray * NCHUNK + chunk] = cnt;
}

// ---------------------------------------------------------------------------
// Merge: WARP per ray. Lane = chunk. Batched (MLP=8) candidate loads into a
// per-lane sorted top-10; 10 rounds of warp-wide 64-bit min-reduce over
// (sortable(t)<<32 | idx): exact stable tie-break. Epilogue on lanes 0..9.
// ---------------------------------------------------------------------------
__global__ void __launch_bounds__(256)
merge_kernel(const float* __restrict__ rays_o, const float* __restrict__ rays_d,
             const float* __restrict__ features_dc, const float* __restrict__ opacity,
             float* __restrict__ out) {
    const int warp = threadIdx.x >> 5;
    const int lane = threadIdx.x & 31;
    const int ray  = blockIdx.x * (blockDim.x >> 5) + warp;

    float d[TOPK];
    int   id[TOPK];
#pragma unroll
    for (int j = 0; j < TOPK; ++j) { d[j] = CUDART_INF_F; id[j] = 0; }

    {
        int n = g_cnt[ray * NCHUNK + lane];
        n = n < CAP ? n : CAP;
        const float2* __restrict__ buf = g_buf + (ray * NCHUNK + lane) * CAP;
        for (int j0 = 0; j0 < n; j0 += 8) {
            float2 e[8];
#pragma unroll
            for (int s = 0; s < 8; ++s)
                e[s] = (j0 + s < n) ? buf[j0 + s] : make_float2(CUDART_INF_F, 0.0f);
#pragma unroll
            for (int s = 0; s < 8; ++s) {
                float tv = e[s].x;
                if (tv < d[TOPK - 1]) {
                    int i = __float_as_int(e[s].y);
                    int pos = TOPK - 1;
#pragma unroll
                    for (int r = TOPK - 1; r > 0; --r) {
                        if (tv < d[r - 1]) { d[r] = d[r - 1]; id[r] = id[r - 1]; pos = r - 1; }
                    }
                    d[pos] = tv; id[pos] = i;
                }
            }
        }
    }

    // 10 rounds of warp min selection over per-lane sorted list heads
    int h = 0;
    unsigned long long cur =
        ((unsigned long long)f2sort(d[0]) << 32) | (unsigned)id[0];
    unsigned long long sel = 0xFFFFFFFFFFFFFFFFull;

#pragma unroll
    for (int r = 0; r < TOPK; ++r) {
        unsigned long long k = cur;
#pragma unroll
        for (int off = 16; off > 0; off >>= 1) {
            unsigned long long o = __shfl_xor_sync(0xFFFFFFFFu, k, off);
            k = o < k ? o : k;
        }
        if (lane == r) sel = k;
        if (cur == k) {  // unique keys (distinct idx): exactly one owner pops
            ++h;
            cur = (h < TOPK)
                ? (((unsigned long long)f2sort(d[h]) << 32) | (unsigned)id[h])
                : 0xFFFFFFFFFFFFFFFFull;
        }
    }

    float cx, cy, cz;
    ray_center(rays_o, rays_d, ray, cx, cy, cz);
    const float c2 = fmaf(cx, cx, fmaf(cy, cy, cz * cz));

    float w = 0.f, wr = 0.f, wg = 0.f, wb = 0.f;
    if (lane < TOPK) {
        const int   k    = (int)(unsigned)sel;
        const float tv   = sort2f((unsigned)(sel >> 32));
        const float sq   = fmaxf(tv + c2, 0.0f);
        const float dist = sqrtf(sq);
        const float op   = 1.0f / (1.0f + expf(-opacity[k]));
        w  = expf(-0.1f * dist) * op;
        wr = w * (1.0f / (1.0f + expf(-features_dc[3 * k + 0])));
        wg = w * (1.0f / (1.0f + expf(-features_dc[3 * k + 1])));
        wb = w * (1.0f / (1.0f + expf(-features_dc[3 * k + 2])));
    }
#pragma unroll
    for (int off = 16; off > 0; off >>= 1) {
        w  += __shfl_xor_sync(0xFFFFFFFFu, w,  off);
        wr += __shfl_xor_sync(0xFFFFFFFFu, wr, off);
        wg += __shfl_xor_sync(0xFFFFFFFFu, wg, off);
        wb += __shfl_xor_sync(0xFFFFFFFFu, wb, off);
    }
    if (lane == 0) {
        const float inv = 1.0f / (w + 1e-8f);
        out[3 * ray + 0] = wr * inv;
        out[3 * ray + 1] = wg * inv;
        out[3 * ray + 2] = wb * inv;
    }
}

// ---------------------------------------------------------------------------
// Launch
// ---------------------------------------------------------------------------
extern "C" void kernel_launch(void* const* d_in, const int* in_sizes, int n_in,
                              void* d_out, int out_size) {
    const float* rays_o      = (const float*)d_in[0];
    const float* rays_d      = (const float*)d_in[1];
    const float* xyz         = (const float*)d_in[2];
    const float* features_dc = (const float*)d_in[3];
    const float* opacity     = (const float*)d_in[4];
    float* out = (float*)d_out;

    prep_kernel<<<(NPAIR + 255) / 256, 256>>>(xyz);

    dim3 tgrid(NGROUP / GPB, NTAUCH);                 // (16, 8)
    tau_part_kernel<<<tgrid, GPB * 32>>>(rays_o, rays_d);
    tau_combine_kernel<<<BATCH / 256, 256>>>();

    dim3 sgrid(NGROUP / GPB, NCHUNK);                 // (16, 32)
    scan_kernel<<<sgrid, GPB * 32>>>(rays_o, rays_d);

    merge_kernel<<<BATCH / 8, 256>>>(rays_o, rays_d, features_dc, opacity, out);
}